// round 9
// baseline (speedup 1.0000x reference)
#include <cuda_runtime.h>
#include <cuda_bf16.h>
#include <cstdint>

constexpr int B = 8;
constexpr int X = 2048;
constexpr int Y = 2048;
constexpr int H = 1024;

constexpr int CPB   = 128;         // chunks per batch (finer for wave balance)
constexpr int YC    = Y / CPB;     // 16 rows per chunk
constexpr int RPW   = YC / 8;      // 2 rows per warp
constexpr int XROWS = 32;          // output rows per bcast block

// Scratch (allocation-free __device__ globals)
__device__ float g_part[B * CPB * H];   // 4 MB per-chunk weighted v-sums
__device__ float g_psum[B * CPB];       // per-chunk exp-sums
__device__ float g_o   [B * H];         // normalized output row per batch

// -------------------------------------------------------------------------
// K1: warp-local fused dot+exp+weighted-sum over a 16-row Y-chunk.
// 1024 blocks (6.9 logical waves, dynamically scheduled -> ~no tail idle).
// Each warp owns 2 rows end-to-end: dot (xor-reduce, all lanes) -> exp ->
// 8 reg-float4 v-accumulate. No block barrier in mainloop.
//
// Math: softmax_y(sk[x]+sq[y]+b) shift-invariant -> k,b cancel; weights
// independent of x. |sq|~N(0,0.5) -> exp safe without max-subtraction.
// -------------------------------------------------------------------------
__global__ __launch_bounds__(256) void k_part(const float* __restrict__ q,
                                              const float* __restrict__ v,
                                              const float* __restrict__ W) {
    const int id   = blockIdx.x;          // 0..1023
    const int b    = id >> 7;
    const int c    = id & (CPB - 1);
    const int t    = threadIdx.x;
    const int warp = t >> 5;
    const int lane = t & 31;

    __shared__ float  wq[H];              // 4 KB
    __shared__ float4 red[8 * (H / 4)];   // 32 KB fold buffer
    __shared__ float  wsum[8];

    for (int i = t; i < H; i += 256) wq[i] = W[H + i];
    __syncthreads();

    const size_t rowbase = (size_t)b * Y + ((size_t)c * YC + warp * RPW);
    const float4* w4 = reinterpret_cast<const float4*>(wq);

    // ---- Phase A: both rows' dot products (16 front-batched loads) -------
    const float4* qr0 = reinterpret_cast<const float4*>(q + rowbase * H);
    const float4* qr1 = reinterpret_cast<const float4*>(q + (rowbase + 1) * H);
    float s0 = 0.f, s1 = 0.f;
#pragma unroll
    for (int i = 0; i < 8; ++i) {
        const float4 a0 = __ldcs(&qr0[lane + i * 32]);
        const float4 a1 = __ldcs(&qr1[lane + i * 32]);
        const float4 wv = w4[lane + i * 32];
        s0 += a0.x * wv.x + a0.y * wv.y + a0.z * wv.z + a0.w * wv.w;
        s1 += a1.x * wv.x + a1.y * wv.y + a1.z * wv.z + a1.w * wv.w;
    }
#pragma unroll
    for (int o = 16; o; o >>= 1) {
        s0 += __shfl_xor_sync(0xFFFFFFFFu, s0, o);
        s1 += __shfl_xor_sync(0xFFFFFFFFu, s1, o);
    }
    const float e0 = __expf(s0);
    const float e1 = __expf(s1);

    // ---- Phase B: v-accumulate both rows ---------------------------------
    const float4* vr0 = reinterpret_cast<const float4*>(v + rowbase * H);
    const float4* vr1 = reinterpret_cast<const float4*>(v + (rowbase + 1) * H);
    float4 acc[8];
#pragma unroll
    for (int i = 0; i < 8; ++i) {
        const float4 v0 = __ldcs(&vr0[lane + i * 32]);
        const float4 v1 = __ldcs(&vr1[lane + i * 32]);
        acc[i].x = e0 * v0.x + e1 * v1.x;
        acc[i].y = e0 * v0.y + e1 * v1.y;
        acc[i].z = e0 * v0.z + e1 * v1.z;
        acc[i].w = e0 * v0.w + e1 * v1.w;
    }

    // ---- Fold 8 warps through shared -------------------------------------
    float4* slab = &red[warp * (H / 4)];
#pragma unroll
    for (int i = 0; i < 8; ++i) slab[lane + i * 32] = acc[i];
    if (lane == 0) wsum[warp] = e0 + e1;
    __syncthreads();

    float4 tot = make_float4(0.f, 0.f, 0.f, 0.f);
#pragma unroll
    for (int w = 0; w < 8; ++w) {
        const float4 x = red[w * (H / 4) + t];
        tot.x += x.x; tot.y += x.y; tot.z += x.z; tot.w += x.w;
    }
    reinterpret_cast<float4*>(&g_part[(size_t)id * H])[t] = tot;

    if (t == 0) {
        float s = 0.f;
#pragma unroll
        for (int w = 0; w < 8; ++w) s += wsum[w];
        g_psum[id] = s;
    }
}

// -------------------------------------------------------------------------
// K1.5: g_o[b,h] = (sum_c g_part[b,c,h]) / (sum_c g_psum[b,c]).  L2-hot.
// 32 blocks, 256 threads.
// -------------------------------------------------------------------------
__global__ __launch_bounds__(256) void k_reduce() {
    const int bx = blockIdx.x;            // 0..31
    const int b  = bx >> 2;
    const int h  = (bx & 3) * 256 + threadIdx.x;

    __shared__ float ssum[CPB];
    if (threadIdx.x < CPB) ssum[threadIdx.x] = g_psum[b * CPB + threadIdx.x];
    __syncthreads();

    float s = 0.f;
#pragma unroll
    for (int c = 0; c < CPB; ++c) s += ssum[c];

    float acc = 0.f;
#pragma unroll 8
    for (int c = 0; c < CPB; ++c)
        acc += __ldcg(&g_part[((size_t)(b * CPB + c)) * H + h]);

    g_o[b * H + h] = acc / s;
}

// -------------------------------------------------------------------------
// K2: out[b,x,:] = g_o[b,:]; register-held float4, 32 streaming row-stores
// per thread (STG.128 at LSU issue floor). 512 blocks.
// -------------------------------------------------------------------------
__global__ __launch_bounds__(256) void k_bcast(float* __restrict__ out) {
    const int bid  = blockIdx.x;          // 0..511
    const int b    = bid >> 6;
    const int slab = bid & 63;

    const float4 val = __ldcg(reinterpret_cast<const float4*>(&g_o[b * H]) + threadIdx.x);

    float4* o4 = reinterpret_cast<float4*>(out) +
                 ((size_t)b * X + (size_t)slab * XROWS) * (H / 4) + threadIdx.x;
#pragma unroll
    for (int x = 0; x < XROWS; ++x)
        __stcs(&o4[(size_t)x * (H / 4)], val);
}

// -------------------------------------------------------------------------
// Inputs: q (B,Y,H) f32, k [UNUSED - cancels], v (B,Y,H) f32, W (2H,) f32,
// b [UNUSED - cancels]. Output (B,X,H) f32.
// -------------------------------------------------------------------------
extern "C" void kernel_launch(void* const* d_in, const int* in_sizes, int n_in,
                              void* d_out, int out_size) {
    const float* q = (const float*)d_in[0];
    const float* v = (const float*)d_in[2];
    const float* W = (const float*)d_in[3];
    float* out = (float*)d_out;

    k_part  <<<B * CPB, 256>>>(q, v, W);
    k_reduce<<<B * 4,   256>>>();
    k_bcast <<<B * 64,  256>>>(out);
}